// round 3
// baseline (speedup 1.0000x reference)
#include <cuda_runtime.h>
#include <math.h>
#include <stdint.h>

#define BB 131072
#define HD 1024

// ---------------- scratch (device globals; no allocation) ----------------
__device__ float g_h1[(size_t)BB * HD];   // 512MB: h1, later h3
__device__ float g_h2[(size_t)BB * HD];   // 512MB: h2
__device__ float g_act[(size_t)BB * HD];  // 512MB: tf32-rounded activations
__device__ float g_w2t[HD * HD];          // tf32-rounded W2
__device__ float g_w3t[HD * HD];          // tf32-rounded W3
__device__ float g_ps[1024 * HD];         // partial column sums
__device__ float g_pq[1024 * HD];         // partial column sumsq
__device__ float g_scale[HD];
__device__ float g_shift[HD];

// ---------------- helpers ----------------
__device__ __forceinline__ unsigned tf32_bits(float x) {
    unsigned u;
    asm("cvt.rna.tf32.f32 %0, %1;" : "=r"(u) : "f"(x));
    return u;
}

// ---------------- layer1: h1 = x @ W1 + b1 (K=3, fp32) + partial stats ----
// 512 blocks x 256 rows; thread owns 4 consecutive columns.
__global__ void k_layer1(const float* __restrict__ x, const float* __restrict__ W1,
                         const float* __restrict__ b1, float* __restrict__ h,
                         float* __restrict__ ps, float* __restrict__ pq) {
    __shared__ float xs[256 * 3];
    const int blk = blockIdx.x;
    const int tid = threadIdx.x;
    const int row0 = blk * 256;
    for (int i = tid; i < 768; i += 256) xs[i] = x[(size_t)row0 * 3 + i];
    __syncthreads();

    const int c = tid * 4;
    float w0[4], w1[4], w2[4], bb[4];
#pragma unroll
    for (int e = 0; e < 4; e++) {
        w0[e] = W1[c + e];
        w1[e] = W1[HD + c + e];
        w2[e] = W1[2 * HD + c + e];
        bb[e] = b1[c + e];
    }
    float s[4] = {0.f, 0.f, 0.f, 0.f}, q[4] = {0.f, 0.f, 0.f, 0.f};
    for (int r = 0; r < 256; r++) {
        float x0 = xs[3 * r], x1 = xs[3 * r + 1], x2 = xs[3 * r + 2];
        float v[4];
#pragma unroll
        for (int e = 0; e < 4; e++) {
            float t = fmaf(x0, w0[e], bb[e]);
            t = fmaf(x1, w1[e], t);
            t = fmaf(x2, w2[e], t);
            v[e] = t;
            s[e] += t;
            q[e] = fmaf(t, t, q[e]);
        }
        float4 st = make_float4(v[0], v[1], v[2], v[3]);
        *(float4*)(h + (size_t)(row0 + r) * HD + c) = st;
    }
#pragma unroll
    for (int e = 0; e < 4; e++) {
        ps[(size_t)blk * HD + c + e] = s[e];
        pq[(size_t)blk * HD + c + e] = q[e];
    }
}

// ---------------- column stats over a 128-row block (deterministic) -------
__global__ void k_stats(const float* __restrict__ h, float* __restrict__ ps,
                        float* __restrict__ pq) {
    const int blk = blockIdx.x;
    const int tid = threadIdx.x;
    const int row0 = blk * 128;
    const int c = tid * 4;
    float s[4] = {0.f, 0.f, 0.f, 0.f}, q[4] = {0.f, 0.f, 0.f, 0.f};
    for (int r = 0; r < 128; r++) {
        float4 v = *(const float4*)(h + (size_t)(row0 + r) * HD + c);
        s[0] += v.x; q[0] = fmaf(v.x, v.x, q[0]);
        s[1] += v.y; q[1] = fmaf(v.y, v.y, q[1]);
        s[2] += v.z; q[2] = fmaf(v.z, v.z, q[2]);
        s[3] += v.w; q[3] = fmaf(v.w, v.w, q[3]);
    }
#pragma unroll
    for (int e = 0; e < 4; e++) {
        ps[(size_t)blk * HD + c + e] = s[e];
        pq[(size_t)blk * HD + c + e] = q[e];
    }
}

// ---------------- reduce partials -> per-column scale/shift ---------------
__global__ void k_reduce(const float* __restrict__ ps, const float* __restrict__ pq,
                         const float* __restrict__ g, const float* __restrict__ bt,
                         float* __restrict__ scale, float* __restrict__ shift, int parts) {
    const int c = blockIdx.x * blockDim.x + threadIdx.x;
    if (c >= HD) return;
    float s = 0.f, q = 0.f;
    for (int p = 0; p < parts; p++) {
        s += ps[(size_t)p * HD + c];
        q += pq[(size_t)p * HD + c];
    }
    const float invB = 1.0f / (float)BB;
    float mu = s * invB;
    float var = fmaxf(q * invB - mu * mu, 0.f);
    float sc = g[c] * rsqrtf(var + 1e-5f);
    scale[c] = sc;
    shift[c] = bt[c] - mu * sc;
}

// ---------------- activation: act = tf32(relu(h*scale+shift)) -------------
__global__ void k_act(const float* __restrict__ h, const float* __restrict__ scale,
                      const float* __restrict__ shift, float* __restrict__ act) {
    const size_t i = (size_t)blockIdx.x * 256 + threadIdx.x;  // one float4
    const int c = ((int)(i & 255)) * 4;                       // HD/4 == 256
    float4 v = ((const float4*)h)[i];
    float4 o;
    o.x = __uint_as_float(tf32_bits(fmaxf(fmaf(v.x, scale[c + 0], shift[c + 0]), 0.f)));
    o.y = __uint_as_float(tf32_bits(fmaxf(fmaf(v.y, scale[c + 1], shift[c + 1]), 0.f)));
    o.z = __uint_as_float(tf32_bits(fmaxf(fmaf(v.z, scale[c + 2], shift[c + 2]), 0.f)));
    o.w = __uint_as_float(tf32_bits(fmaxf(fmaf(v.w, scale[c + 3], shift[c + 3]), 0.f)));
    ((float4*)act)[i] = o;
}

// ---------------- weight round to tf32 ------------------------------------
__global__ void k_cvtw(const float* __restrict__ w, float* __restrict__ o) {
    const size_t i = (size_t)blockIdx.x * 256 + threadIdx.x;  // one float4
    float4 v = ((const float4*)w)[i];
    float4 r;
    r.x = __uint_as_float(tf32_bits(v.x));
    r.y = __uint_as_float(tf32_bits(v.y));
    r.z = __uint_as_float(tf32_bits(v.z));
    r.w = __uint_as_float(tf32_bits(v.w));
    ((float4*)o)[i] = r;
}

// ---------------- TF32 GEMM: C[BBxHD] = A[BBxHD] @ W[HDxHD] + bias --------
// CTA tile 128x128x32, 8 warps (2x4), m16n8k8 tf32 mma.sync, cp.async 2-stage.
#define ASTR 36
#define BSTR 136
#define ASZ (128 * ASTR)  // 4608 floats
#define BSZ (32 * BSTR)   // 4352 floats
#define GEMM_SMEM_BYTES (2 * (ASZ + BSZ) * 4)  // 71680

__global__ void __launch_bounds__(256, 2)
k_gemm(const float* __restrict__ A, const float* __restrict__ Bw,
       const float* __restrict__ bias, float* __restrict__ C) {
    extern __shared__ float sm[];
    const int tid = threadIdx.x;
    const int m0 = blockIdx.y * 128;
    const int n0 = blockIdx.x * 128;

    const unsigned smA = (unsigned)__cvta_generic_to_shared(sm);
    const unsigned smB = smA + 2u * ASZ * 4u;

    // A loads: 1024 float4 per tile, 4 per thread: rows (tid>>3)+32j, qword tid&7
    const int ar = tid >> 3, aq = tid & 7;
    // B loads: rows (tid>>5)+8j, qword tid&31
    const int br = tid >> 5, bq = tid & 31;

    const float* Ag = A + (size_t)(m0 + ar) * HD + aq * 4;
    const float* Bg = Bw + (size_t)br * HD + n0 + bq * 4;
    const unsigned aS = (unsigned)(ar * ASTR + aq * 4) * 4u;
    const unsigned bS = (unsigned)(br * BSTR + bq * 4) * 4u;

    auto load_tile = [&](int stage, int k0) {
        unsigned a_s = smA + (unsigned)stage * (ASZ * 4u) + aS;
        const float* a_g = Ag + k0;
#pragma unroll
        for (int j = 0; j < 4; j++) {
            asm volatile("cp.async.cg.shared.global [%0], [%1], 16;" ::"r"(
                             a_s + (unsigned)(j * 32 * ASTR * 4)),
                         "l"(a_g + (size_t)32 * HD * j));
        }
        unsigned b_s = smB + (unsigned)stage * (BSZ * 4u) + bS;
        const float* b_g = Bg + (size_t)k0 * HD;
#pragma unroll
        for (int j = 0; j < 4; j++) {
            asm volatile("cp.async.cg.shared.global [%0], [%1], 16;" ::"r"(
                             b_s + (unsigned)(j * 8 * BSTR * 4)),
                         "l"(b_g + (size_t)8 * HD * j));
        }
        asm volatile("cp.async.commit_group;");
    };

    float acc[4][4][4];
#pragma unroll
    for (int a = 0; a < 4; a++)
#pragma unroll
        for (int b = 0; b < 4; b++)
#pragma unroll
            for (int c = 0; c < 4; c++) acc[a][b][c] = 0.f;

    const int lane = tid & 31, ly = lane >> 2, lx = lane & 3;
    const int wm = ((tid >> 5) & 1) * 64;
    const int wn = (tid >> 6) * 32;

    load_tile(0, 0);
#pragma unroll 1
    for (int t = 0; t < 32; t++) {
        if (t < 31) {
            load_tile((t + 1) & 1, (t + 1) * 32);
            asm volatile("cp.async.wait_group 1;");
        } else {
            asm volatile("cp.async.wait_group 0;");
        }
        __syncthreads();
        const float* As = sm + (t & 1) * ASZ;
        const float* Bs = sm + 2 * ASZ + (t & 1) * BSZ;
#pragma unroll
        for (int kk = 0; kk < 32; kk += 8) {
            unsigned af[4][4], bf[4][2];
#pragma unroll
            for (int mi = 0; mi < 4; mi++) {
                const float* p = As + (wm + mi * 16 + ly) * ASTR + kk + lx;
                af[mi][0] = __float_as_uint(p[0]);
                af[mi][1] = __float_as_uint(p[8 * ASTR]);
                af[mi][2] = __float_as_uint(p[4]);
                af[mi][3] = __float_as_uint(p[8 * ASTR + 4]);
            }
#pragma unroll
            for (int ni = 0; ni < 4; ni++) {
                const float* p = Bs + (kk + lx) * BSTR + wn + ni * 8 + ly;
                bf[ni][0] = __float_as_uint(p[0]);
                bf[ni][1] = __float_as_uint(p[4 * BSTR]);
            }
#pragma unroll
            for (int mi = 0; mi < 4; mi++)
#pragma unroll
                for (int ni = 0; ni < 4; ni++) {
                    asm volatile(
                        "mma.sync.aligned.m16n8k8.row.col.f32.tf32.tf32.f32 "
                        "{%0,%1,%2,%3}, {%4,%5,%6,%7}, {%8,%9}, {%0,%1,%2,%3};"
                        : "+f"(acc[mi][ni][0]), "+f"(acc[mi][ni][1]),
                          "+f"(acc[mi][ni][2]), "+f"(acc[mi][ni][3])
                        : "r"(af[mi][0]), "r"(af[mi][1]), "r"(af[mi][2]), "r"(af[mi][3]),
                          "r"(bf[ni][0]), "r"(bf[ni][1]));
                }
        }
        __syncthreads();
    }

#pragma unroll
    for (int mi = 0; mi < 4; mi++) {
        const int r0 = m0 + wm + mi * 16 + ly;
#pragma unroll
        for (int ni = 0; ni < 4; ni++) {
            const int c = n0 + wn + ni * 8 + 2 * lx;
            const float bc0 = bias[c], bc1 = bias[c + 1];
            float2 v0 = make_float2(acc[mi][ni][0] + bc0, acc[mi][ni][1] + bc1);
            float2 v1 = make_float2(acc[mi][ni][2] + bc0, acc[mi][ni][3] + bc1);
            *(float2*)(C + (size_t)r0 * HD + c) = v0;
            *(float2*)(C + (size_t)(r0 + 8) * HD + c) = v1;
        }
    }
}

// ---------------- final: thetas = relu(bn(h3)) @ W4 + b4; kinematics ------
__device__ __forceinline__ void dh_mat(float M[3][4], float th, float r, float ca,
                                       float sa) {
    float ct = cosf(th), st = sinf(th);
    M[0][0] = ct;  M[0][1] = -st * ca; M[0][2] = st * sa;  M[0][3] = r * ct;
    M[1][0] = st;  M[1][1] = ct * ca;  M[1][2] = -ct * sa; M[1][3] = r * st;
    M[2][0] = 0.f; M[2][1] = sa;       M[2][2] = ca;       M[2][3] = 0.f;
}

__device__ __forceinline__ void matmul34(const float A[3][4], const float Bm[3][4],
                                         float C[3][4]) {
#pragma unroll
    for (int i = 0; i < 3; i++) {
#pragma unroll
        for (int j = 0; j < 4; j++) {
            float v = A[i][0] * Bm[0][j] + A[i][1] * Bm[1][j] + A[i][2] * Bm[2][j];
            if (j == 3) v += A[i][3];
            C[i][j] = v;
        }
    }
}

__global__ void k_final(const float* __restrict__ h3, const float* __restrict__ scale,
                        const float* __restrict__ shift, const float* __restrict__ W4,
                        const float* __restrict__ b4, float* __restrict__ out) {
    __shared__ float w4s[3072];
    __shared__ float b4s[3];
    const int tid = threadIdx.x;
    for (int i = tid; i < 3072; i += 256) w4s[i] = W4[i];
    if (tid < 3) b4s[tid] = b4[tid];
    __syncthreads();

    const int lane = tid & 31;
    const size_t row = (size_t)blockIdx.x * 8 + (tid >> 5);
    const float* hr = h3 + row * HD;
    float t0 = 0.f, t1 = 0.f, t2 = 0.f;
    for (int k = lane; k < HD; k += 32) {
        float a = fmaxf(fmaf(hr[k], scale[k], shift[k]), 0.f);
        t0 = fmaf(a, w4s[3 * k + 0], t0);
        t1 = fmaf(a, w4s[3 * k + 1], t1);
        t2 = fmaf(a, w4s[3 * k + 2], t2);
    }
#pragma unroll
    for (int o = 16; o > 0; o >>= 1) {
        t0 += __shfl_xor_sync(0xffffffffu, t0, o);
        t1 += __shfl_xor_sync(0xffffffffu, t1, o);
        t2 += __shfl_xor_sync(0xffffffffu, t2, o);
    }
    if (lane == 0) {
        const float th0 = t0 + b4s[0];
        const float th1 = t1 + b4s[1];
        const float th2 = t2 + b4s[2];
        out[row * 3 + 0] = th0;
        out[row * 3 + 1] = th1;
        out[row * 3 + 2] = th2;

        const float PI2 = 1.57079632679489661923f;  // fl(pi/2), matches jnp
        float M[3][4], Nn[3][4], P[3][4];
        dh_mat(M, th0, 0.f, cosf(PI2), sinf(PI2));
        dh_mat(Nn, th1, 0.12f, 1.f, 0.f);
        matmul34(M, Nn, P);
        dh_mat(Nn, th2, 0.115f, 1.f, 0.f);
        matmul34(P, Nn, M);
        float* op = out + (size_t)BB * 3 + row * 3;
        op[0] = M[0][3];
        op[1] = M[1][3];
        op[2] = M[2][3];
    }
}

// ---------------- launch ---------------------------------------------------
extern "C" void kernel_launch(void* const* d_in, const int* in_sizes, int n_in,
                              void* d_out, int out_size) {
    const float* x   = (const float*)d_in[0];
    const float* W1  = (const float*)d_in[1];
    const float* b1  = (const float*)d_in[2];
    const float* g1  = (const float*)d_in[3];
    const float* bt1 = (const float*)d_in[4];
    const float* W2  = (const float*)d_in[5];
    const float* b2  = (const float*)d_in[6];
    const float* g2  = (const float*)d_in[7];
    const float* bt2 = (const float*)d_in[8];
    const float* W3  = (const float*)d_in[9];
    const float* b3  = (const float*)d_in[10];
    const float* g3  = (const float*)d_in[11];
    const float* bt3 = (const float*)d_in[12];
    const float* W4  = (const float*)d_in[13];
    const float* b4  = (const float*)d_in[14];
    float* out = (float*)d_out;

    void *p_h1, *p_h2, *p_act, *p_w2t, *p_w3t, *p_ps, *p_pq, *p_sc, *p_sh;
    cudaGetSymbolAddress(&p_h1, g_h1);
    cudaGetSymbolAddress(&p_h2, g_h2);
    cudaGetSymbolAddress(&p_act, g_act);
    cudaGetSymbolAddress(&p_w2t, g_w2t);
    cudaGetSymbolAddress(&p_w3t, g_w3t);
    cudaGetSymbolAddress(&p_ps, g_ps);
    cudaGetSymbolAddress(&p_pq, g_pq);
    cudaGetSymbolAddress(&p_sc, g_scale);
    cudaGetSymbolAddress(&p_sh, g_shift);
    float* h1 = (float*)p_h1;
    float* h2 = (float*)p_h2;
    float* act = (float*)p_act;
    float* w2t = (float*)p_w2t;
    float* w3t = (float*)p_w3t;
    float* ps = (float*)p_ps;
    float* pq = (float*)p_pq;
    float* sc = (float*)p_sc;
    float* sh = (float*)p_sh;

    cudaFuncSetAttribute(k_gemm, cudaFuncAttributeMaxDynamicSharedMemorySize,
                         GEMM_SMEM_BYTES);

    const int actBlocks = (int)((size_t)BB * HD / 4 / 256);  // 131072
    const dim3 gemmGrid(8, BB / 128);                        // n fastest -> L2 A reuse

    // round weights to tf32 once per call
    k_cvtw<<<HD * HD / 4 / 256, 256>>>(W2, w2t);
    k_cvtw<<<HD * HD / 4 / 256, 256>>>(W3, w3t);

    // layer 1 (fp32 exact) + fused partial stats
    k_layer1<<<BB / 256, 256>>>(x, W1, b1, h1, ps, pq);
    k_reduce<<<4, 256>>>(ps, pq, g1, bt1, sc, sh, BB / 256);
    k_act<<<actBlocks, 256>>>(h1, sc, sh, act);

    // layer 2
    k_gemm<<<gemmGrid, 256, GEMM_SMEM_BYTES>>>(act, w2t, b2, h2);
    k_stats<<<BB / 128, 256>>>(h2, ps, pq);
    k_reduce<<<4, 256>>>(ps, pq, g2, bt2, sc, sh, BB / 128);
    k_act<<<actBlocks, 256>>>(h2, sc, sh, act);

    // layer 3 (h3 reuses h1 buffer)
    k_gemm<<<gemmGrid, 256, GEMM_SMEM_BYTES>>>(act, w3t, b3, h1);
    k_stats<<<BB / 128, 256>>>(h1, ps, pq);
    k_reduce<<<4, 256>>>(ps, pq, g3, bt3, sc, sh, BB / 128);

    // final layer (fp32, BN fused) + forward kinematics
    k_final<<<BB / 8, 256>>>(h1, sc, sh, W4, b4, out);
}

// round 7
// speedup vs baseline: 1.1045x; 1.1045x over previous
#include <cuda_runtime.h>
#include <math.h>
#include <stdint.h>

#define BB 131072
#define HD 1024

// ---------------- scratch (device globals; no allocation) ----------------
__device__ float g_h2[(size_t)BB * HD];   // 512MB: h2
__device__ float g_h3[(size_t)BB * HD];   // 512MB: h3
__device__ float g_act[(size_t)BB * HD];  // 512MB: tf32-rounded activations
__device__ float g_w2t[HD * HD];          // tf32-rounded W2
__device__ float g_w3t[HD * HD];          // tf32-rounded W3
__device__ float g_ps[1024 * HD];         // partial column sums
__device__ float g_pq[1024 * HD];         // partial column sumsq
__device__ float g_scale[HD];
__device__ float g_shift[HD];

// ---------------- helpers ----------------
__device__ __forceinline__ unsigned tf32_bits(float x) {
    unsigned u;
    asm("cvt.rna.tf32.f32 %0, %1;" : "=r"(u) : "f"(x));
    return u;
}

// ---------------- layer1 stats: partial sums of x@W1+b1 (no h store) ------
__global__ void k_layer1_stats(const float* __restrict__ x,
                               const float* __restrict__ W1,
                               const float* __restrict__ b1,
                               float* __restrict__ ps, float* __restrict__ pq) {
    __shared__ float xs[256 * 3];
    const int blk = blockIdx.x;
    const int tid = threadIdx.x;
    const int row0 = blk * 256;
    for (int i = tid; i < 768; i += 256) xs[i] = x[(size_t)row0 * 3 + i];
    __syncthreads();

    const int c = tid * 4;
    float w0[4], w1[4], w2[4], bb[4];
#pragma unroll
    for (int e = 0; e < 4; e++) {
        w0[e] = W1[c + e];
        w1[e] = W1[HD + c + e];
        w2[e] = W1[2 * HD + c + e];
        bb[e] = b1[c + e];
    }
    float s[4] = {0.f, 0.f, 0.f, 0.f}, q[4] = {0.f, 0.f, 0.f, 0.f};
    for (int r = 0; r < 256; r++) {
        float x0 = xs[3 * r], x1 = xs[3 * r + 1], x2 = xs[3 * r + 2];
#pragma unroll
        for (int e = 0; e < 4; e++) {
            float t = fmaf(x0, w0[e], bb[e]);
            t = fmaf(x1, w1[e], t);
            t = fmaf(x2, w2[e], t);
            s[e] += t;
            q[e] = fmaf(t, t, q[e]);
        }
    }
#pragma unroll
    for (int e = 0; e < 4; e++) {
        ps[(size_t)blk * HD + c + e] = s[e];
        pq[(size_t)blk * HD + c + e] = q[e];
    }
}

// ---------------- layer1 act: recompute h1 from x, BN+ReLU+tf32 -> act ----
__global__ void k_act1(const float* __restrict__ x, const float* __restrict__ W1,
                       const float* __restrict__ b1, const float* __restrict__ scale,
                       const float* __restrict__ shift, float* __restrict__ act) {
    __shared__ float xs[256 * 3];
    const int blk = blockIdx.x;
    const int tid = threadIdx.x;
    const int row0 = blk * 256;
    for (int i = tid; i < 768; i += 256) xs[i] = x[(size_t)row0 * 3 + i];
    __syncthreads();

    const int c = tid * 4;
    float w0[4], w1[4], w2[4], bb[4], sc[4], sh[4];
#pragma unroll
    for (int e = 0; e < 4; e++) {
        w0[e] = W1[c + e];
        w1[e] = W1[HD + c + e];
        w2[e] = W1[2 * HD + c + e];
        bb[e] = b1[c + e];
        sc[e] = scale[c + e];
        sh[e] = shift[c + e];
    }
    for (int r = 0; r < 256; r++) {
        float x0 = xs[3 * r], x1 = xs[3 * r + 1], x2 = xs[3 * r + 2];
        float v[4];
#pragma unroll
        for (int e = 0; e < 4; e++) {
            float t = fmaf(x0, w0[e], bb[e]);
            t = fmaf(x1, w1[e], t);
            t = fmaf(x2, w2[e], t);
            v[e] = __uint_as_float(tf32_bits(fmaxf(fmaf(t, sc[e], sh[e]), 0.f)));
        }
        *(float4*)(act + (size_t)(row0 + r) * HD + c) =
            make_float4(v[0], v[1], v[2], v[3]);
    }
}

// ---------------- reduce partials -> per-column scale/shift (1 blk/col) ---
__global__ void k_reduce2(const float* __restrict__ ps, const float* __restrict__ pq,
                          const float* __restrict__ g, const float* __restrict__ bt,
                          float* __restrict__ scale, float* __restrict__ shift,
                          int parts) {
    const int c = blockIdx.x;
    const int tid = threadIdx.x;
    float s = 0.f, q = 0.f;
    for (int p = tid; p < parts; p += 256) {
        s += ps[(size_t)p * HD + c];
        q += pq[(size_t)p * HD + c];
    }
    __shared__ float ss[8], qq[8];
#pragma unroll
    for (int o = 16; o; o >>= 1) {
        s += __shfl_xor_sync(0xffffffffu, s, o);
        q += __shfl_xor_sync(0xffffffffu, q, o);
    }
    if ((tid & 31) == 0) { ss[tid >> 5] = s; qq[tid >> 5] = q; }
    __syncthreads();
    if (tid == 0) {
        float S = 0.f, Q = 0.f;
#pragma unroll
        for (int w = 0; w < 8; w++) { S += ss[w]; Q += qq[w]; }
        const float invB = 1.0f / (float)BB;
        float mu = S * invB;
        float var = fmaxf(Q * invB - mu * mu, 0.f);
        float sc = g[c] * rsqrtf(var + 1e-5f);
        scale[c] = sc;
        shift[c] = bt[c] - mu * sc;
    }
}

// ---------------- activation: act = tf32(relu(h*scale+shift)) -------------
__global__ void k_act(const float* __restrict__ h, const float* __restrict__ scale,
                      const float* __restrict__ shift, float* __restrict__ act) {
    const size_t i = (size_t)blockIdx.x * 256 + threadIdx.x;  // one float4
    const int c = ((int)(i & 255)) * 4;                       // HD/4 == 256
    float4 v = ((const float4*)h)[i];
    float4 o;
    o.x = __uint_as_float(tf32_bits(fmaxf(fmaf(v.x, scale[c + 0], shift[c + 0]), 0.f)));
    o.y = __uint_as_float(tf32_bits(fmaxf(fmaf(v.y, scale[c + 1], shift[c + 1]), 0.f)));
    o.z = __uint_as_float(tf32_bits(fmaxf(fmaf(v.z, scale[c + 2], shift[c + 2]), 0.f)));
    o.w = __uint_as_float(tf32_bits(fmaxf(fmaf(v.w, scale[c + 3], shift[c + 3]), 0.f)));
    ((float4*)act)[i] = o;
}

// ---------------- weight round to tf32 ------------------------------------
__global__ void k_cvtw(const float* __restrict__ w, float* __restrict__ o) {
    const size_t i = (size_t)blockIdx.x * 256 + threadIdx.x;  // one float4
    float4 v = ((const float4*)w)[i];
    float4 r;
    r.x = __uint_as_float(tf32_bits(v.x));
    r.y = __uint_as_float(tf32_bits(v.y));
    r.z = __uint_as_float(tf32_bits(v.z));
    r.w = __uint_as_float(tf32_bits(v.w));
    ((float4*)o)[i] = r;
}

// ---------------- TF32 GEMM: C[BBxHD] = A[BBxHD] @ W[HDxHD] + bias --------
// CTA tile 128x128x32, 8 warps (2x4), m16n8k8 tf32 mma.sync, cp.async 2-stage.
// Fused: per-CTA column sum/sumsq of C (over the CTA's 128 rows) -> ps/pq.
#define ASTR 36
#define BSTR 136
#define ASZ (128 * ASTR)  // 4608 floats
#define BSZ (32 * BSTR)   // 4352 floats
#define GEMM_SMEM_BYTES (2 * (ASZ + BSZ) * 4)  // 71680

__global__ void __launch_bounds__(256, 2)
k_gemm(const float* __restrict__ A, const float* __restrict__ Bw,
       const float* __restrict__ bias, float* __restrict__ C,
       float* __restrict__ ps, float* __restrict__ pq) {
    extern __shared__ float sm[];
    __shared__ float sred[8][32], qred[8][32];
    const int tid = threadIdx.x;
    const int m0 = blockIdx.y * 128;
    const int n0 = blockIdx.x * 128;

    const unsigned smA = (unsigned)__cvta_generic_to_shared(sm);
    const unsigned smB = smA + 2u * ASZ * 4u;

    // A loads: 1024 float4 per tile, 4 per thread: rows (tid>>3)+32j, qword tid&7
    const int ar = tid >> 3, aq = tid & 7;
    // B loads: rows (tid>>5)+8j, qword tid&31
    const int br = tid >> 5, bq = tid & 31;

    const float* Ag = A + (size_t)(m0 + ar) * HD + aq * 4;
    const float* Bg = Bw + (size_t)br * HD + n0 + bq * 4;
    const unsigned aS = (unsigned)(ar * ASTR + aq * 4) * 4u;
    const unsigned bS = (unsigned)(br * BSTR + bq * 4) * 4u;

    auto load_tile = [&](int stage, int k0) {
        unsigned a_s = smA + (unsigned)stage * (ASZ * 4u) + aS;
        const float* a_g = Ag + k0;
#pragma unroll
        for (int j = 0; j < 4; j++) {
            asm volatile("cp.async.cg.shared.global [%0], [%1], 16;" ::"r"(
                             a_s + (unsigned)(j * 32 * ASTR * 4)),
                         "l"(a_g + (size_t)32 * HD * j));
        }
        unsigned b_s = smB + (unsigned)stage * (BSZ * 4u) + bS;
        const float* b_g = Bg + (size_t)k0 * HD;
#pragma unroll
        for (int j = 0; j < 4; j++) {
            asm volatile("cp.async.cg.shared.global [%0], [%1], 16;" ::"r"(
                             b_s + (unsigned)(j * 8 * BSTR * 4)),
                         "l"(b_g + (size_t)8 * HD * j));
        }
        asm volatile("cp.async.commit_group;");
    };

    float acc[4][4][4];
#pragma unroll
    for (int a = 0; a < 4; a++)
#pragma unroll
        for (int b = 0; b < 4; b++)
#pragma unroll
            for (int c = 0; c < 4; c++) acc[a][b][c] = 0.f;

    const int lane = tid & 31, ly = lane >> 2, lx = lane & 3;
    const int wid = tid >> 5;
    const int wm = (wid & 1) * 64;
    const int wn = (tid >> 6) * 32;

    load_tile(0, 0);
#pragma unroll 1
    for (int t = 0; t < 32; t++) {
        if (t < 31) {
            load_tile((t + 1) & 1, (t + 1) * 32);
            asm volatile("cp.async.wait_group 1;");
        } else {
            asm volatile("cp.async.wait_group 0;");
        }
        __syncthreads();
        const float* As = sm + (t & 1) * ASZ;
        const float* Bs = sm + 2 * ASZ + (t & 1) * BSZ;
#pragma unroll
        for (int kk = 0; kk < 32; kk += 8) {
            unsigned af[4][4], bf[4][2];
#pragma unroll
            for (int mi = 0; mi < 4; mi++) {
                const float* p = As + (wm + mi * 16 + ly) * ASTR + kk + lx;
                af[mi][0] = __float_as_uint(p[0]);
                af[mi][1] = __float_as_uint(p[8 * ASTR]);
                af[mi][2] = __float_as_uint(p[4]);
                af[mi][3] = __float_as_uint(p[8 * ASTR + 4]);
            }
#pragma unroll
            for (int ni = 0; ni < 4; ni++) {
                const float* p = Bs + (kk + lx) * BSTR + wn + ni * 8 + ly;
                bf[ni][0] = __float_as_uint(p[0]);
                bf[ni][1] = __float_as_uint(p[4 * BSTR]);
            }
#pragma unroll
            for (int mi = 0; mi < 4; mi++)
#pragma unroll
                for (int ni = 0; ni < 4; ni++) {
                    asm volatile(
                        "mma.sync.aligned.m16n8k8.row.col.f32.tf32.tf32.f32 "
                        "{%0,%1,%2,%3}, {%4,%5,%6,%7}, {%8,%9}, {%0,%1,%2,%3};"
                        : "+f"(acc[mi][ni][0]), "+f"(acc[mi][ni][1]),
                          "+f"(acc[mi][ni][2]), "+f"(acc[mi][ni][3])
                        : "r"(af[mi][0]), "r"(af[mi][1]), "r"(af[mi][2]), "r"(af[mi][3]),
                          "r"(bf[ni][0]), "r"(bf[ni][1]));
                }
        }
        __syncthreads();
    }

    // Epilogue: store C = acc + bias, and accumulate per-column s/q partials.
    float sc_[4][2] = {{0.f, 0.f}, {0.f, 0.f}, {0.f, 0.f}, {0.f, 0.f}};
    float qc_[4][2] = {{0.f, 0.f}, {0.f, 0.f}, {0.f, 0.f}, {0.f, 0.f}};
#pragma unroll
    for (int mi = 0; mi < 4; mi++) {
        const int r0 = m0 + wm + mi * 16 + ly;
#pragma unroll
        for (int ni = 0; ni < 4; ni++) {
            const int c = n0 + wn + ni * 8 + 2 * lx;
            const float bc0 = bias[c], bc1 = bias[c + 1];
            float2 v0 = make_float2(acc[mi][ni][0] + bc0, acc[mi][ni][1] + bc1);
            float2 v1 = make_float2(acc[mi][ni][2] + bc0, acc[mi][ni][3] + bc1);
            *(float2*)(C + (size_t)r0 * HD + c) = v0;
            *(float2*)(C + (size_t)(r0 + 8) * HD + c) = v1;
            sc_[ni][0] += v0.x + v1.x;
            sc_[ni][1] += v0.y + v1.y;
            qc_[ni][0] = fmaf(v0.x, v0.x, fmaf(v1.x, v1.x, qc_[ni][0]));
            qc_[ni][1] = fmaf(v0.y, v0.y, fmaf(v1.y, v1.y, qc_[ni][1]));
        }
    }
    // reduce over ly (lanes with same lx): xor 4, 8, 16
#pragma unroll
    for (int ni = 0; ni < 4; ni++) {
#pragma unroll
        for (int j = 0; j < 2; j++) {
            float s = sc_[ni][j], q = qc_[ni][j];
#pragma unroll
            for (int o = 4; o <= 16; o <<= 1) {
                s += __shfl_xor_sync(0xffffffffu, s, o);
                q += __shfl_xor_sync(0xffffffffu, q, o);
            }
            if (lane < 4) {
                sred[wid][ni * 8 + 2 * lx + j] = s;
                qred[wid][ni * 8 + 2 * lx + j] = q;
            }
        }
    }
    __syncthreads();
    if (tid < 128) {
        const int col = tid;
        const int gpair = (col >> 5) * 2;   // warps (gpair, gpair+1) own this group
        const int cc = col & 31;
        ps[(size_t)blockIdx.y * HD + n0 + col] = sred[gpair][cc] + sred[gpair + 1][cc];
        pq[(size_t)blockIdx.y * HD + n0 + col] = qred[gpair][cc] + qred[gpair + 1][cc];
    }
}

// ---------------- final: thetas = relu(bn(h3)) @ W4 + b4; kinematics ------
__device__ __forceinline__ void dh_mat(float M[3][4], float th, float r, float ca,
                                       float sa) {
    float ct = cosf(th), st = sinf(th);
    M[0][0] = ct;  M[0][1] = -st * ca; M[0][2] = st * sa;  M[0][3] = r * ct;
    M[1][0] = st;  M[1][1] = ct * ca;  M[1][2] = -ct * sa; M[1][3] = r * st;
    M[2][0] = 0.f; M[2][1] = sa;       M[2][2] = ca;       M[2][3] = 0.f;
}

__device__ __forceinline__ void matmul34(const float A[3][4], const float Bm[3][4],
                                         float C[3][4]) {
#pragma unroll
    for (int i = 0; i < 3; i++) {
#pragma unroll
        for (int j = 0; j < 4; j++) {
            float v = A[i][0] * Bm[0][j] + A[i][1] * Bm[1][j] + A[i][2] * Bm[2][j];
            if (j == 3) v += A[i][3];
            C[i][j] = v;
        }
    }
}

__global__ void k_final(const float* __restrict__ h3, const float* __restrict__ scale,
                        const float* __restrict__ shift, const float* __restrict__ W4,
                        const float* __restrict__ b4, float* __restrict__ out) {
    __shared__ float w4s[3072];
    __shared__ float b4s[3];
    const int tid = threadIdx.x;
    for (int i = tid; i < 3072; i += 256) w4s[i] = W4[i];
    if (tid < 3) b4s[tid] = b4[tid];
    __syncthreads();

    const int lane = tid & 31;
    const size_t row = (size_t)blockIdx.x * 8 + (tid >> 5);
    const float* hr = h3 + row * HD;
    float t0 = 0.f, t1 = 0.f, t2 = 0.f;
    for (int k = lane; k < HD; k += 32) {
        float a = fmaxf(fmaf(hr[k], scale[k], shift[k]), 0.f);
        t0 = fmaf(a, w4s[3 * k + 0], t0);
        t1 = fmaf(a, w4s[3 * k + 1], t1);
        t2 = fmaf(a, w4s[3 * k + 2], t2);
    }
#pragma unroll
    for (int o = 16; o > 0; o >>= 1) {
        t0 += __shfl_xor_sync(0xffffffffu, t0, o);
        t1 += __shfl_xor_sync(0xffffffffu, t1, o);
        t2 += __shfl_xor_sync(0xffffffffu, t2, o);
    }
    if (lane == 0) {
        const float th0 = t0 + b4s[0];
        const float th1 = t1 + b4s[1];
        const float th2 = t2 + b4s[2];
        out[row * 3 + 0] = th0;
        out[row * 3 + 1] = th1;
        out[row * 3 + 2] = th2;

        const float PI2 = 1.57079632679489661923f;
        float M[3][4], Nn[3][4], P[3][4];
        dh_mat(M, th0, 0.f, cosf(PI2), sinf(PI2));
        dh_mat(Nn, th1, 0.12f, 1.f, 0.f);
        matmul34(M, Nn, P);
        dh_mat(Nn, th2, 0.115f, 1.f, 0.f);
        matmul34(P, Nn, M);
        float* op = out + (size_t)BB * 3 + row * 3;
        op[0] = M[0][3];
        op[1] = M[1][3];
        op[2] = M[2][3];
    }
}

// ---------------- launch ---------------------------------------------------
extern "C" void kernel_launch(void* const* d_in, const int* in_sizes, int n_in,
                              void* d_out, int out_size) {
    const float* x   = (const float*)d_in[0];
    const float* W1  = (const float*)d_in[1];
    const float* b1  = (const float*)d_in[2];
    const float* g1  = (const float*)d_in[3];
    const float* bt1 = (const float*)d_in[4];
    const float* W2  = (const float*)d_in[5];
    const float* b2  = (const float*)d_in[6];
    const float* g2  = (const float*)d_in[7];
    const float* bt2 = (const float*)d_in[8];
    const float* W3  = (const float*)d_in[9];
    const float* b3  = (const float*)d_in[10];
    const float* g3  = (const float*)d_in[11];
    const float* bt3 = (const float*)d_in[12];
    const float* W4  = (const float*)d_in[13];
    const float* b4  = (const float*)d_in[14];
    float* out = (float*)d_out;

    void *p_h2, *p_h3, *p_act, *p_w2t, *p_w3t, *p_ps, *p_pq, *p_sc, *p_sh;
    cudaGetSymbolAddress(&p_h2, g_h2);
    cudaGetSymbolAddress(&p_h3, g_h3);
    cudaGetSymbolAddress(&p_act, g_act);
    cudaGetSymbolAddress(&p_w2t, g_w2t);
    cudaGetSymbolAddress(&p_w3t, g_w3t);
    cudaGetSymbolAddress(&p_ps, g_ps);
    cudaGetSymbolAddress(&p_pq, g_pq);
    cudaGetSymbolAddress(&p_sc, g_scale);
    cudaGetSymbolAddress(&p_sh, g_shift);
    float* h2 = (float*)p_h2;
    float* h3 = (float*)p_h3;
    float* act = (float*)p_act;
    float* w2t = (float*)p_w2t;
    float* w3t = (float*)p_w3t;
    float* ps = (float*)p_ps;
    float* pq = (float*)p_pq;
    float* sc = (float*)p_sc;
    float* sh = (float*)p_sh;

    cudaFuncSetAttribute(k_gemm, cudaFuncAttributeMaxDynamicSharedMemorySize,
                         GEMM_SMEM_BYTES);

    const int actBlocks = (int)((size_t)BB * HD / 4 / 256);  // 131072
    const dim3 gemmGrid(8, BB / 128);                        // n fastest -> A L2 reuse

    // round weights to tf32 once per call
    k_cvtw<<<HD * HD / 4 / 256, 256>>>(W2, w2t);
    k_cvtw<<<HD * HD / 4 / 256, 256>>>(W3, w3t);

    // layer 1: stats only (no h1 materialization), then recompute+act
    k_layer1_stats<<<BB / 256, 256>>>(x, W1, b1, ps, pq);
    k_reduce2<<<HD, 256>>>(ps, pq, g1, bt1, sc, sh, BB / 256);
    k_act1<<<BB / 256, 256>>>(x, W1, b1, sc, sh, act);

    // layer 2: GEMM with fused column stats
    k_gemm<<<gemmGrid, 256, GEMM_SMEM_BYTES>>>(act, w2t, b2, h2, ps, pq);
    k_reduce2<<<HD, 256>>>(ps, pq, g2, bt2, sc, sh, BB / 128);
    k_act<<<actBlocks, 256>>>(h2, sc, sh, act);

    // layer 3: GEMM with fused column stats
    k_gemm<<<gemmGrid, 256, GEMM_SMEM_BYTES>>>(act, w3t, b3, h3, ps, pq);
    k_reduce2<<<HD, 256>>>(ps, pq, g3, bt3, sc, sh, BB / 128);

    // final layer (fp32, BN fused) + forward kinematics
    k_final<<<BB / 8, 256>>>(h3, sc, sh, W4, b4, out);
}